// round 17
// baseline (speedup 1.0000x reference)
#include <cuda_runtime.h>
#include <cuda_fp16.h>

#define N_NODES 4096
#define FIN     128
#define NH      4
#define FOUT    64
#define HF      256
#define MAXD    256
#define NBLK    1536   // b%3 in {0,1} -> scan (1024 blocks, 1 row/warp), b%3==2 -> GEMM (512)
#define ESCALE  (1.0f / 4096.0f)

// -------- device scratch --------
__device__ __half g_h2[NH * N_NODES * FOUT];     // fp16 [h][n][f] (2 MB), 128B/row
__device__ float  g_ss[N_NODES * NH];            // src score [n][h]
__device__ float  g_st[N_NODES * NH];            // tgt score [n][h] (float4-loadable)
__device__ float  g_skip[N_NODES * HF];          // skip proj result
__device__ unsigned short g_adj[(size_t)N_NODES * MAXD];
__device__ int    g_deg[N_NODES];

static __device__ __forceinline__ unsigned pack_half2(float a, float b) {
    const __half2 h = __floats2half2_rn(a, b);
    return *(const unsigned*)&h;
}

union F2U { float2 f; unsigned long long u; };

static __device__ __forceinline__ void add_f32x2(unsigned long long& acc,
                                                 unsigned long long v) {
    asm("add.rn.f32x2 %0, %1, %0;" : "+l"(acc) : "l"(v));
}

static __device__ __forceinline__ __half2 u2h(unsigned u) {
    return *(const __half2*)&u;
}

// ============================================================
// Fat kernel (R15-proven, unchanged). b%3==2: tensor-core GEMM;
// else: mask scan, warp per row.
// ============================================================
__global__ __launch_bounds__(128) void prep_kernel(
    const float* __restrict__ x,
    const float* __restrict__ mask,
    const float* __restrict__ proj,
    const float* __restrict__ score_src,
    const float* __restrict__ score_tgt,
    const float* __restrict__ skip_w)
{
    __shared__ uint4 xs4[64 * 16];   // A tile (16 KB)
    __shared__ uint4 ws4[128 * 8];   // B tile (16 KB)
    __shared__ float redS[2][64], redT[2][64];

    const int b   = blockIdx.x;
    const int tid = threadIdx.x;

    if (b % 3 != 2) {
        // ---------------- scan role: warp per row ----------------
        const int sb   = (b / 3) * 2 + (b % 3);    // 0..1023
        const int wid  = tid >> 5;
        const int lane = tid & 31;
        const int row  = sb * 4 + wid;
        const float4* mr = (const float4*)(mask + (size_t)row * N_NODES);
        unsigned short* adj = g_adj + (size_t)row * MAXD;
        const unsigned lt = (1u << lane) - 1u;
        int base = 0;
#pragma unroll 16
        for (int g = 0; g < N_NODES / 128; g++) {
            const float4 v = mr[g * 32 + lane];
            const unsigned b0 = __ballot_sync(0xffffffffu, v.x == 0.f);
            const unsigned b1 = __ballot_sync(0xffffffffu, v.y == 0.f);
            const unsigned b2 = __ballot_sync(0xffffffffu, v.z == 0.f);
            const unsigned b3 = __ballot_sync(0xffffffffu, v.w == 0.f);
            const int c0 = __popc(b0), c1 = __popc(b1), c2 = __popc(b2), c3 = __popc(b3);
            const int e0 = g * 128 + lane * 4;
            if (v.x == 0.f) { int p = base + __popc(b0 & lt);                if (p < MAXD) adj[p] = (unsigned short)(e0);     }
            if (v.y == 0.f) { int p = base + c0 + __popc(b1 & lt);           if (p < MAXD) adj[p] = (unsigned short)(e0 + 1); }
            if (v.z == 0.f) { int p = base + c0 + c1 + __popc(b2 & lt);      if (p < MAXD) adj[p] = (unsigned short)(e0 + 2); }
            if (v.w == 0.f) { int p = base + c0 + c1 + c2 + __popc(b3 & lt); if (p < MAXD) adj[p] = (unsigned short)(e0 + 3); }
            base += c0 + c1 + c2 + c3;
        }
        if (lane == 0) g_deg[row] = min(base, MAXD);
        return;
    }

    // ---------------- GEMM role ----------------
    const int gb = b / 3;            // 0..511
    const int rt = gb >> 3;          // row tile 0..63
    const int ct = gb & 7;           // col tile 0..7
    const int r0 = rt * 64;
    const int w    = tid >> 5;       // warp 0..3
    const int lane = tid & 31;
    const int wr = (w >> 1) * 32;
    const int wc = (w & 1) * 32;

    // ---- stage A ----
    {
        const float4* xg = (const float4*)(x + (size_t)r0 * FIN);
#pragma unroll
        for (int i = 0; i < 8; i++) {
            const int idx = tid + i * 128;
            const int r = idx >> 4, c8 = idx & 15;
            const float4 v0 = xg[r * 32 + c8 * 2];
            const float4 v1 = xg[r * 32 + c8 * 2 + 1];
            uint4 pk;
            pk.x = pack_half2(v0.x, v0.y);
            pk.y = pack_half2(v0.z, v0.w);
            pk.z = pack_half2(v1.x, v1.y);
            pk.w = pack_half2(v1.z, v1.w);
            xs4[r * 16 + (c8 ^ (r & 7))] = pk;
        }
    }
    // ---- stage B ----
    if (ct >= 4) {
        const float4* wg = (const float4*)(skip_w + (size_t)((ct - 4) * 64) * FIN);
#pragma unroll
        for (int i = 0; i < 8; i++) {
            const int idx = tid + i * 128;
            const int r = idx >> 4, c8 = idx & 15;
            const float4 v0 = wg[r * 32 + c8 * 2];
            const float4 v1 = wg[r * 32 + c8 * 2 + 1];
            uint4 pk;
            pk.x = pack_half2(v0.x, v0.y);
            pk.y = pack_half2(v0.z, v0.w);
            pk.z = pack_half2(v1.x, v1.y);
            pk.w = pack_half2(v1.z, v1.w);
            ws4[r * 16 + (c8 ^ (r & 7))] = pk;
        }
    } else {
        const float4* pg = (const float4*)(proj + (size_t)ct * FIN * FOUT);
#pragma unroll
        for (int i = 0; i < 8; i++) {
            const int idx = tid + i * 128;
            const int r = idx >> 3, c8 = idx & 7;
            const float4 v0 = pg[r * 16 + c8 * 2];
            const float4 v1 = pg[r * 16 + c8 * 2 + 1];
            uint4 pk;
            pk.x = pack_half2(v0.x, v0.y);
            pk.y = pack_half2(v0.z, v0.w);
            pk.z = pack_half2(v1.x, v1.y);
            pk.w = pack_half2(v1.z, v1.w);
            ws4[r * 8 + (c8 ^ (r & 7))] = pk;
        }
    }
    __syncthreads();

    // ---- mma compute ----
    float acc[2][4][4];
#pragma unroll
    for (int mi = 0; mi < 2; mi++)
#pragma unroll
        for (int ni = 0; ni < 4; ni++)
#pragma unroll
            for (int t = 0; t < 4; t++) acc[mi][ni][t] = 0.f;

    const unsigned xsb = (unsigned)__cvta_generic_to_shared(xs4);
    const unsigned wsb = (unsigned)__cvta_generic_to_shared(ws4);

#pragma unroll
    for (int kc = 0; kc < 8; kc++) {
        unsigned a[2][4];
#pragma unroll
        for (int mi = 0; mi < 2; mi++) {
            const int rl = wr + mi * 16 + (lane & 15);
            const int ch = kc * 2 + (lane >> 4);
            const unsigned ad = xsb + rl * 256 + ((ch ^ (rl & 7)) << 4);
            asm volatile("ldmatrix.sync.aligned.m8n8.x4.shared.b16 {%0,%1,%2,%3}, [%4];"
                         : "=r"(a[mi][0]), "=r"(a[mi][1]), "=r"(a[mi][2]), "=r"(a[mi][3])
                         : "r"(ad));
        }
        unsigned bf[4][2];
        if (ct >= 4) {
#pragma unroll
            for (int ni = 0; ni < 4; ni++) {
                const int cl = wc + ni * 8 + (lane & 7);
                const int ch = kc * 2 + ((lane >> 3) & 1);
                const unsigned ad = wsb + cl * 256 + ((ch ^ (cl & 7)) << 4);
                asm volatile("ldmatrix.sync.aligned.m8n8.x2.shared.b16 {%0,%1}, [%2];"
                             : "=r"(bf[ni][0]), "=r"(bf[ni][1])
                             : "r"(ad));
            }
        } else {
#pragma unroll
            for (int ni = 0; ni < 4; ni++) {
                const int k  = kc * 16 + (lane & 15);
                const int c8 = (wc >> 3) + ni;
                const unsigned ad = wsb + (k * 8 + (c8 ^ (k & 7))) * 16;
                asm volatile("ldmatrix.sync.aligned.m8n8.x2.trans.shared.b16 {%0,%1}, [%2];"
                             : "=r"(bf[ni][0]), "=r"(bf[ni][1])
                             : "r"(ad));
            }
        }
#pragma unroll
        for (int mi = 0; mi < 2; mi++)
#pragma unroll
            for (int ni = 0; ni < 4; ni++)
                asm volatile("mma.sync.aligned.m16n8k16.row.col.f32.f16.f16.f32 "
                             "{%0,%1,%2,%3}, {%4,%5,%6,%7}, {%8,%9}, {%0,%1,%2,%3};"
                             : "+f"(acc[mi][ni][0]), "+f"(acc[mi][ni][1]),
                               "+f"(acc[mi][ni][2]), "+f"(acc[mi][ni][3])
                             : "r"(a[mi][0]), "r"(a[mi][1]), "r"(a[mi][2]), "r"(a[mi][3]),
                               "r"(bf[ni][0]), "r"(bf[ni][1]));
    }

    // ---- epilogue ----
    const int g   = lane >> 2;
    const int tig = lane & 3;
    if (ct < 4) {
        const int h = ct;
#pragma unroll
        for (int mi = 0; mi < 2; mi++) {
            const int lr1 = wr + mi * 16 + g;
            const int lr2 = lr1 + 8;
            float sS1 = 0.f, sT1 = 0.f, sS2 = 0.f, sT2 = 0.f;
#pragma unroll
            for (int ni = 0; ni < 4; ni++) {
                const int c0c = wc + ni * 8 + tig * 2;
                const float sv0 = score_src[h * FOUT + c0c];
                const float sv1 = score_src[h * FOUT + c0c + 1];
                const float tv0 = score_tgt[h * FOUT + c0c];
                const float tv1 = score_tgt[h * FOUT + c0c + 1];
                const float2 hi = {acc[mi][ni][0], acc[mi][ni][1]};
                const float2 lo = {acc[mi][ni][2], acc[mi][ni][3]};
                *(unsigned*)((char*)g_h2 + (((size_t)h * N_NODES + r0 + lr1) * FOUT + c0c) * 2) = pack_half2(hi.x, hi.y);
                *(unsigned*)((char*)g_h2 + (((size_t)h * N_NODES + r0 + lr2) * FOUT + c0c) * 2) = pack_half2(lo.x, lo.y);
                sS1 += hi.x * sv0 + hi.y * sv1;  sT1 += hi.x * tv0 + hi.y * tv1;
                sS2 += lo.x * sv0 + lo.y * sv1;  sT2 += lo.x * tv0 + lo.y * tv1;
            }
#pragma unroll
            for (int o = 1; o < 4; o <<= 1) {
                sS1 += __shfl_xor_sync(0xffffffffu, sS1, o);
                sT1 += __shfl_xor_sync(0xffffffffu, sT1, o);
                sS2 += __shfl_xor_sync(0xffffffffu, sS2, o);
                sT2 += __shfl_xor_sync(0xffffffffu, sT2, o);
            }
            if (tig == 0) {
                redS[w & 1][lr1] = sS1;  redT[w & 1][lr1] = sT1;
                redS[w & 1][lr2] = sS2;  redT[w & 1][lr2] = sT2;
            }
        }
        __syncthreads();
        if (tid < 64) {
            g_ss[(r0 + tid) * NH + h] = redS[0][tid] + redS[1][tid];
            g_st[(r0 + tid) * NH + h] = redT[0][tid] + redT[1][tid];
        }
    } else {
        const int c0g = (ct - 4) * 64;
#pragma unroll
        for (int mi = 0; mi < 2; mi++) {
            const int lr1 = wr + mi * 16 + g;
            const int lr2 = lr1 + 8;
#pragma unroll
            for (int ni = 0; ni < 4; ni++) {
                const int cc = c0g + wc + ni * 8 + tig * 2;
                const float2 hi = {acc[mi][ni][0], acc[mi][ni][1]};
                const float2 lo = {acc[mi][ni][2], acc[mi][ni][3]};
                *(float2*)(g_skip + (size_t)(r0 + lr1) * HF + cc) = hi;
                *(float2*)(g_skip + (size_t)(r0 + lr2) * HF + cc) = lo;
            }
        }
    }
}

// ============================================================
// Attention kernel: fp16 gathers, 8 lanes x LDG.128 per neighbor
// -> 4 j's in flight per warp iteration. fp16 product chains
// (<=4 terms, e pre-scaled by 1/4096), packed-fp32 flush.
// Lane q8 owns feats 8*q8 .. 8*q8+7.
// ============================================================
__global__ __launch_bounds__(128) void attn_kernel(
    const float* __restrict__ bias,
    float* __restrict__ out)
{
    const int n    = blockIdx.x;
    const int tid  = threadIdx.x;
    const int h    = tid >> 5;
    const int lane = tid & 31;

    __shared__ uint2 pair[NH][MAXD];     // {half2(e*c, e*c), byte offset} — 8 KB
    __shared__ float partS[NH][NH + 1];

    const int deg = g_deg[n];
    const float4 ss4 = *(const float4*)(g_ss + (size_t)n * NH);
    const float4* st4 = (const float4*)g_st;
    const unsigned short* adj = g_adj + (size_t)n * MAXD;

    float s0 = 0.f, s1 = 0.f, s2 = 0.f, s3 = 0.f;
    for (int j = tid; j < deg; j += 128) {
        const int m = adj[j];
        const float4 st = st4[m];
        float v0 = ss4.x + st.x; v0 = v0 > 0.f ? v0 : 0.2f * v0;
        float v1 = ss4.y + st.y; v1 = v1 > 0.f ? v1 : 0.2f * v1;
        float v2 = ss4.z + st.z; v2 = v2 > 0.f ? v2 : 0.2f * v2;
        float v3 = ss4.w + st.w; v3 = v3 > 0.f ? v3 : 0.2f * v3;
        const float e0 = __expf(v0), e1 = __expf(v1);
        const float e2 = __expf(v2), e3 = __expf(v3);
        const unsigned off = (unsigned)(m * (FOUT * 2));   // byte offset of fp16 row
        pair[0][j] = make_uint2(pack_half2(e0 * ESCALE, e0 * ESCALE), off);
        pair[1][j] = make_uint2(pack_half2(e1 * ESCALE, e1 * ESCALE), off);
        pair[2][j] = make_uint2(pack_half2(e2 * ESCALE, e2 * ESCALE), off);
        pair[3][j] = make_uint2(pack_half2(e3 * ESCALE, e3 * ESCALE), off);
        s0 += e0; s1 += e1; s2 += e2; s3 += e3;
    }
#pragma unroll
    for (int o = 16; o; o >>= 1) {
        s0 += __shfl_xor_sync(0xffffffffu, s0, o);
        s1 += __shfl_xor_sync(0xffffffffu, s1, o);
        s2 += __shfl_xor_sync(0xffffffffu, s2, o);
        s3 += __shfl_xor_sync(0xffffffffu, s3, o);
    }
    if (lane == 0) {
        partS[h][0] = s0; partS[h][1] = s1;
        partS[h][2] = s2; partS[h][3] = s3;
    }
    __syncthreads();
    const float S = partS[0][h] + partS[1][h] + partS[2][h] + partS[3][h];

    // gather: subgroup sg (8 lanes) handles j = sg, sg+4, ...; lane q8 -> 16 bytes (8 halves)
    const int sg = lane >> 3;
    const int q8 = lane & 7;
    const char* hb = (const char*)g_h2 + (size_t)h * N_NODES * (FOUT * 2) + q8 * 16;
    unsigned long long a01 = 0, a23 = 0, a45 = 0, a67 = 0;   // packed {f32,f32}
    int j = sg;
    for (; j + 12 < deg; j += 16) {
        const uint2 P0 = pair[h][j];
        const uint2 P1 = pair[h][j + 4];
        const uint2 P2 = pair[h][j + 8];
        const uint2 P3 = pair[h][j + 12];
        const uint4 H0 = *(const uint4*)(hb + P0.y);
        const uint4 H1 = *(const uint4*)(hb + P1.y);
        const uint4 H2 = *(const uint4*)(hb + P2.y);
        const uint4 H3 = *(const uint4*)(hb + P3.y);
        __half2 c0 = __hmul2(u2h(P0.x), u2h(H0.x));
        __half2 c1 = __hmul2(u2h(P0.x), u2h(H0.y));
        __half2 c2 = __hmul2(u2h(P0.x), u2h(H0.z));
        __half2 c3 = __hmul2(u2h(P0.x), u2h(H0.w));
        c0 = __hfma2(u2h(P1.x), u2h(H1.x), c0);
        c1 = __hfma2(u2h(P1.x), u2h(H1.y), c1);
        c2 = __hfma2(u2h(P1.x), u2h(H1.z), c2);
        c3 = __hfma2(u2h(P1.x), u2h(H1.w), c3);
        c0 = __hfma2(u2h(P2.x), u2h(H2.x), c0);
        c1 = __hfma2(u2h(P2.x), u2h(H2.y), c1);
        c2 = __hfma2(u2h(P2.x), u2h(H2.z), c2);
        c3 = __hfma2(u2h(P2.x), u2h(H2.w), c3);
        c0 = __hfma2(u2h(P3.x), u2h(H3.x), c0);
        c1 = __hfma2(u2h(P3.x), u2h(H3.y), c1);
        c2 = __hfma2(u2h(P3.x), u2h(H3.z), c2);
        c3 = __hfma2(u2h(P3.x), u2h(H3.w), c3);
        F2U f0; f0.f = __half22float2(c0);
        F2U f1; f1.f = __half22float2(c1);
        F2U f2; f2.f = __half22float2(c2);
        F2U f3; f3.f = __half22float2(c3);
        add_f32x2(a01, f0.u);
        add_f32x2(a23, f1.u);
        add_f32x2(a45, f2.u);
        add_f32x2(a67, f3.u);
    }
    for (; j < deg; j += 4) {
        const uint2 P = pair[h][j];
        const uint4 H = *(const uint4*)(hb + P.y);
        const __half2 c0 = __hmul2(u2h(P.x), u2h(H.x));
        const __half2 c1 = __hmul2(u2h(P.x), u2h(H.y));
        const __half2 c2 = __hmul2(u2h(P.x), u2h(H.z));
        const __half2 c3 = __hmul2(u2h(P.x), u2h(H.w));
        F2U f0; f0.f = __half22float2(c0);
        F2U f1; f1.f = __half22float2(c1);
        F2U f2; f2.f = __half22float2(c2);
        F2U f3; f3.f = __half22float2(c3);
        add_f32x2(a01, f0.u);
        add_f32x2(a23, f1.u);
        add_f32x2(a45, f2.u);
        add_f32x2(a67, f3.u);
    }
    F2U r01; r01.u = a01;
    F2U r23; r23.u = a23;
    F2U r45; r45.u = a45;
    F2U r67; r67.u = a67;
    float a0 = r01.f.x, a1 = r01.f.y, a2 = r23.f.x, a3 = r23.f.y;
    float a4 = r45.f.x, a5 = r45.f.y, a6 = r67.f.x, a7 = r67.f.y;
    // combine the 4 subgroups (lanes differing in bits 3 and 4)
#pragma unroll
    for (int o = 8; o <= 16; o <<= 1) {
        a0 += __shfl_xor_sync(0xffffffffu, a0, o);
        a1 += __shfl_xor_sync(0xffffffffu, a1, o);
        a2 += __shfl_xor_sync(0xffffffffu, a2, o);
        a3 += __shfl_xor_sync(0xffffffffu, a3, o);
        a4 += __shfl_xor_sync(0xffffffffu, a4, o);
        a5 += __shfl_xor_sync(0xffffffffu, a5, o);
        a6 += __shfl_xor_sync(0xffffffffu, a6, o);
        a7 += __shfl_xor_sync(0xffffffffu, a7, o);
    }

    if (lane < 8) {
        const float inv = (1.0f / ESCALE) / S;   // undo e-scaling + normalize
        const int cbase = h * FOUT + q8 * 8;
        const float4 sk0 = *(const float4*)(g_skip + (size_t)n * HF + cbase);
        const float4 sk1 = *(const float4*)(g_skip + (size_t)n * HF + cbase + 4);
        const float4 bi0 = *(const float4*)(bias + cbase);
        const float4 bi1 = *(const float4*)(bias + cbase + 4);
        float o0 = a0 * inv + sk0.x + bi0.x;
        float o1 = a1 * inv + sk0.y + bi0.y;
        float o2 = a2 * inv + sk0.z + bi0.z;
        float o3 = a3 * inv + sk0.w + bi0.w;
        float o4 = a4 * inv + sk1.x + bi1.x;
        float o5 = a5 * inv + sk1.y + bi1.y;
        float o6 = a6 * inv + sk1.z + bi1.z;
        float o7 = a7 * inv + sk1.w + bi1.w;
        o0 = o0 > 0.f ? o0 : (__expf(o0) - 1.f);
        o1 = o1 > 0.f ? o1 : (__expf(o1) - 1.f);
        o2 = o2 > 0.f ? o2 : (__expf(o2) - 1.f);
        o3 = o3 > 0.f ? o3 : (__expf(o3) - 1.f);
        o4 = o4 > 0.f ? o4 : (__expf(o4) - 1.f);
        o5 = o5 > 0.f ? o5 : (__expf(o5) - 1.f);
        o6 = o6 > 0.f ? o6 : (__expf(o6) - 1.f);
        o7 = o7 > 0.f ? o7 : (__expf(o7) - 1.f);
        float* op = out + (size_t)n * HF + cbase;
        *(float4*)op       = make_float4(o0, o1, o2, o3);
        *(float4*)(op + 4) = make_float4(o4, o5, o6, o7);
    }
}

// ============================================================
extern "C" void kernel_launch(void* const* d_in, const int* in_sizes, int n_in,
                              void* d_out, int out_size)
{
    const float* x         = (const float*)d_in[0];
    const float* mask      = (const float*)d_in[1];
    const float* proj      = (const float*)d_in[2];
    const float* score_src = (const float*)d_in[3];
    const float* score_tgt = (const float*)d_in[4];
    const float* skip_w    = (const float*)d_in[5];
    const float* bias      = (const float*)d_in[6];
    float* out             = (float*)d_out;

    prep_kernel<<<NBLK, 128>>>(x, mask, proj, score_src, score_tgt, skip_w);
    attn_kernel<<<N_NODES, 128>>>(bias, out);
}